// round 14
// baseline (speedup 1.0000x reference)
#include <cuda_runtime.h>
#include <math.h>

#define Bn 2
#define Nn 256
#define INDIM 256
#define EDIM 16
#define Hh 8
#define Dd 64
#define INNER 512
#define BHn 16
#define TI 16
#define CH 16
#define ATH 256
#define XSTR 20   // float stride per j-row of xs

typedef unsigned long long u64;

// ---- packed f32x2 helpers (Blackwell FFMA2) ----
__device__ __forceinline__ u64 pk2(float lo, float hi) {
    u64 r;
    asm("mov.b64 %0, {%1, %2};" : "=l"(r)
        : "r"(__float_as_uint(lo)), "r"(__float_as_uint(hi)));
    return r;
}
__device__ __forceinline__ u64 ffma2(u64 a, u64 b, u64 c) {
    u64 d;
    asm("fma.rn.f32x2 %0, %1, %2, %3;" : "=l"(d) : "l"(a), "l"(b), "l"(c));
    return d;
}
__device__ __forceinline__ float2 up2(u64 p) {
    unsigned int lo, hi;
    asm("mov.b64 {%0, %1}, %2;" : "=r"(lo), "=r"(hi) : "l"(p));
    return make_float2(__uint_as_float(lo), __uint_as_float(hi));
}

// ---------------- scratch (device globals; no allocation allowed) ----------------
__device__ float g_q[BHn*Nn*Dd];        // [bh][i][d]
__device__ float g_k[BHn*Nn*Dd];        // [bh][j][d]  (row-major, for means)
__device__ float g_kT[BHn*Dd*Nn];       // [bh][d][j]  (transposed, for attn)
__device__ float g_v[BHn*Nn*Dd];        // [bh][j][d]
__device__ float g_means[Nn];           // row means of sim for bh==0 (reference quirk)
__device__ float4 g_eT4[Bn*Nn*4*Nn];    // [b][i][c4][j] channel-quad-major edges (8.4MB)

// ---------------- fat prep kernel: blocks 0..383 = proj, 384..895 = etr ----------
// Shared-memory alias layout (34432 bytes):
//   proj: As [2][32][36] @ 0 (9216) | Bs [2][32][64] @ 9216 (16384) | TT [32][69] @ 25600 (8832)
//   etr:  es float4[4*Nn] @ 0 (16384)
#define PREP_SMEM 34432

__global__ void __launch_bounds__(128) prep_kernel(
    const float* __restrict__ nodes, const float* __restrict__ edges,
    const float* __restrict__ Wq, const float* __restrict__ bq,
    const float* __restrict__ Wk, const float* __restrict__ bk,
    const float* __restrict__ Wv, const float* __restrict__ bv)
{
    __shared__ __align__(16) char sbuf[PREP_SMEM];
    const int bx = blockIdx.x;
    const int t = threadIdx.x;

    if (bx >= 384) {
        // ================= etr: edge transpose [b][i][j][c] -> [b][i][c4][j] ======
        const int idx = bx - 384;
        const int b = idx >> 8, i = idx & 255;
        float4* es = reinterpret_cast<float4*>(sbuf);   // [c4][j], 16KB
        const float4* ep = reinterpret_cast<const float4*>(edges)
                         + (size_t)(b*Nn + i)*Nn*4;
        #pragma unroll
        for (int r = 0; r < 2; r++) {
            int j = t + r*128;
            #pragma unroll
            for (int c4 = 0; c4 < 4; c4++) es[c4*Nn + j] = ep[j*4 + c4];
        }
        __syncthreads();
        float4* outp = g_eT4 + (size_t)(b*Nn + i)*4*Nn;
        #pragma unroll
        for (int r = 0; r < 8; r++) {
            int k = t + r*128;
            outp[k] = es[k];
        }
        return;
    }

    // ================= proj: double-buffered GEMM, FFMA2, K dual-layout ==========
    const int px = bx & 7, py = (bx >> 3) & 15, which = bx >> 7;
    const float* W    = (which==0) ? Wq : ((which==1) ? Wk : Wv);
    const float* bias = (which==0) ? bq : ((which==1) ? bk : bv);
    typedef float AsT[32][36];
    typedef float BsT[32][64];
    AsT* As = reinterpret_cast<AsT*>(sbuf);                    // As[buf][k][m]
    BsT* Bs = reinterpret_cast<BsT*>(sbuf + 9216);             // Bs[buf][k][n]
    float (*TT)[69] = reinterpret_cast<float(*)[69]>(sbuf + 25600);
    const int row0 = py * 32;
    const int col0 = px * 64;
    const int tx = t & 15, ty = t >> 4;

    u64 acc[4][2];
    #pragma unroll
    for (int u = 0; u < 4; u++) { acc[u][0] = 0ull; acc[u][1] = 0ull; }

    {
        #pragma unroll
        for (int r = 0; r < 2; r++) {
            int idx = t + r*128;
            int row = idx >> 3, kq = idx & 7;
            float4 nv = *reinterpret_cast<const float4*>(&nodes[(row0+row)*INDIM + kq*4]);
            As[0][kq*4+0][row] = nv.x; As[0][kq*4+1][row] = nv.y;
            As[0][kq*4+2][row] = nv.z; As[0][kq*4+3][row] = nv.w;
        }
        #pragma unroll
        for (int r = 0; r < 4; r++) {
            int idx = t + r*128;
            int kk = idx >> 4, c4 = idx & 15;
            *reinterpret_cast<float4*>(&Bs[0][kk][c4*4]) =
                *reinterpret_cast<const float4*>(&W[kk*INNER + col0 + c4*4]);
        }
    }

    #pragma unroll
    for (int it = 0; it < 8; it++) {
        const int p = it & 1;
        __syncthreads();
        if (it < 7) {
            const int k0 = (it+1) * 32;
            const int pn = p ^ 1;
            #pragma unroll
            for (int r = 0; r < 2; r++) {
                int idx = t + r*128;
                int row = idx >> 3, kq = idx & 7;
                float4 nv = *reinterpret_cast<const float4*>(&nodes[(row0+row)*INDIM + k0 + kq*4]);
                As[pn][kq*4+0][row] = nv.x; As[pn][kq*4+1][row] = nv.y;
                As[pn][kq*4+2][row] = nv.z; As[pn][kq*4+3][row] = nv.w;
            }
            #pragma unroll
            for (int r = 0; r < 4; r++) {
                int idx = t + r*128;
                int kk = idx >> 4, c4 = idx & 15;
                *reinterpret_cast<float4*>(&Bs[pn][kk][c4*4]) =
                    *reinterpret_cast<const float4*>(&W[(k0+kk)*INNER + col0 + c4*4]);
            }
        }
        #pragma unroll
        for (int k = 0; k < 32; k++) {
            float4 a4 = *reinterpret_cast<const float4*>(&As[p][k][ty*4]);
            ulonglong2 b2 = *reinterpret_cast<const ulonglong2*>(&Bs[p][k][tx*4]);
            u64 ap;
            ap = pk2(a4.x, a4.x); acc[0][0]=ffma2(b2.x,ap,acc[0][0]); acc[0][1]=ffma2(b2.y,ap,acc[0][1]);
            ap = pk2(a4.y, a4.y); acc[1][0]=ffma2(b2.x,ap,acc[1][0]); acc[1][1]=ffma2(b2.y,ap,acc[1][1]);
            ap = pk2(a4.z, a4.z); acc[2][0]=ffma2(b2.x,ap,acc[2][0]); acc[2][1]=ffma2(b2.y,ap,acc[2][1]);
            ap = pk2(a4.w, a4.w); acc[3][0]=ffma2(b2.x,ap,acc[3][0]); acc[3][1]=ffma2(b2.y,ap,acc[3][1]);
        }
    }

    const int b = row0 >> 8;
    const int i0l = row0 & 255;
    const int h = col0 >> 6;
    const int bh = b*Hh + h;
    float4 bias4 = *reinterpret_cast<const float4*>(&bias[col0 + tx*4]);

    if (which != 1) {
        float* dst = (which == 0) ? g_q : g_v;
        #pragma unroll
        for (int u = 0; u < 4; u++) {
            int i = i0l + ty*4 + u;
            float2 c01 = up2(acc[u][0]);
            float2 c23 = up2(acc[u][1]);
            float4 val = make_float4(c01.x+bias4.x, c01.y+bias4.y,
                                     c23.x+bias4.z, c23.y+bias4.w);
            *reinterpret_cast<float4*>(&dst[(bh*Nn + i)*Dd + tx*4]) = val;
        }
    } else {
        #pragma unroll
        for (int u = 0; u < 4; u++) {
            int i = i0l + ty*4 + u;
            float2 c01 = up2(acc[u][0]);
            float2 c23 = up2(acc[u][1]);
            float4 val = make_float4(c01.x+bias4.x, c01.y+bias4.y,
                                     c23.x+bias4.z, c23.y+bias4.w);
            *reinterpret_cast<float4*>(&g_k[(bh*Nn + i)*Dd + tx*4]) = val;
            int il = ty*4 + u;
            TT[il][tx*4+0] = val.x; TT[il][tx*4+1] = val.y;
            TT[il][tx*4+2] = val.z; TT[il][tx*4+3] = val.w;
        }
        __syncthreads();
        #pragma unroll
        for (int w = 0; w < 16; w++) {
            int idx = t + w*128;               // 2048 = 64 d x 32 i
            int d = idx >> 5, il = idx & 31;
            g_kT[(bh*Dd + d)*Nn + i0l + il] = TT[il][d];
        }
    }
}

// ---------------- means: analytic row-mean ----------------------------------------
__global__ void __launch_bounds__(256) means_kernel(const float* __restrict__ We,
                                                    const float* __restrict__ be)
{
    const int i = blockIdx.x;
    const int t = threadIdx.x;
    const int lane = t & 31, wid = t >> 5;
    __shared__ float qsm[Dd];
    __shared__ float WesM[EDIM*Dd];
    __shared__ float besM[Dd];
    __shared__ float qwes[EDIM];
    __shared__ float qbes_s;
    __shared__ float eParts[8][EDIM];
    __shared__ float kParts[4][Dd];
    __shared__ float esum[EDIM];
    __shared__ float kbar[Dd];

    if (t < Dd) { qsm[t] = g_q[i*Dd + t]; besM[t] = be[t]; }
    #pragma unroll
    for (int r = 0; r < 4; r++) {
        int idx = t + r*256;
        WesM[idx] = We[(idx >> 6)*INNER + (idx & 63)];
    }
    {
        const float4* eTp = g_eT4 + (size_t)i*4*Nn;
        float4 e0 = eTp[0*Nn + t], e1 = eTp[1*Nn + t];
        float4 e2 = eTp[2*Nn + t], e3 = eTp[3*Nn + t];
        float ev[EDIM] = { e0.x,e0.y,e0.z,e0.w, e1.x,e1.y,e1.z,e1.w,
                           e2.x,e2.y,e2.z,e2.w, e3.x,e3.y,e3.z,e3.w };
        #pragma unroll
        for (int c = 0; c < EDIM; c++) {
            float v = ev[c];
            #pragma unroll
            for (int o = 16; o > 0; o >>= 1) v += __shfl_down_sync(0xffffffffu, v, o);
            if (lane == 0) eParts[wid][c] = v;
        }
    }
    {
        const int d = t & 63, jg = t >> 6;
        float s = 0.f;
        #pragma unroll 8
        for (int j = jg; j < Nn; j += 4) s += g_k[j*Dd + d];
        kParts[jg][d] = s;
    }
    __syncthreads();
    if (t < EDIM) {
        float s = 0.f;
        #pragma unroll
        for (int w = 0; w < 8; w++) s += eParts[w][t];
        esum[t] = s;
        float qw = 0.f;
        #pragma unroll
        for (int d = 0; d < Dd; d++) qw += qsm[d] * WesM[t*Dd + d];
        qwes[t] = qw;
    } else if (t == EDIM) {
        float qb = 0.f;
        #pragma unroll
        for (int d = 0; d < Dd; d++) qb += qsm[d] * besM[d];
        qbes_s = qb;
    } else if (t >= 64 && t < 64 + Dd) {
        int d = t - 64;
        kbar[d] = kParts[0][d] + kParts[1][d] + kParts[2][d] + kParts[3][d];
    }
    __syncthreads();
    if (t < 32) {
        float v = qsm[t]*kbar[t] + qsm[t+32]*kbar[t+32];
        if (t < EDIM) v += esum[t]*qwes[t];
        #pragma unroll
        for (int o = 16; o > 0; o >>= 1) v += __shfl_down_sync(0xffffffffu, v, o);
        if (t == 0) g_means[i] = 0.125f * (v * (1.0f/Nn) + qbes_s);
    }
}

// ---------------- fused attention v11: TI=16, 256 thr, 2 blocks/SM ---------------
struct AttnSm {
    float  xs[Nn*XSTR];         // 20K
    float4 red_out[4*Dd*4];     // 16K [g][d][p]
    float4 red_ae[CH*4*4];      // 4K  [u][g2][c4]
    float  qst[Dd*TI];          // 4K  [d][ii]
    float  qwe[TI*EDIM];        // 1K  [ii][c]
    float  Wes[EDIM*Dd];        // 4K  [c][d]
    float  aes[CH*EDIM];        // 1K
    float  red_den[CH*4];
    float  qbe[TI];
    float  mns[TI];
    float  bes[Dd];
    float  den[CH];
};

__global__ void __launch_bounds__(ATH, 2) attn_kernel(
    const float* __restrict__ edges, const float* __restrict__ adjacency,
    const float* __restrict__ We, const float* __restrict__ be,
    float* __restrict__ out)
{
    extern __shared__ char smraw[];
    AttnSm& sm = *reinterpret_cast<AttnSm*>(smraw);
    const int t  = threadIdx.x;
    const int bh = blockIdx.y;
    const int b  = bh >> 3, h = bh & 7;
    const int i0 = blockIdx.x * TI;

    // ---- small tile loads
    #pragma unroll
    for (int r = 0; r < 4; r++) {
        int idx = t + r*ATH;              // 1024 = Dd*TI
        int d = idx >> 4, ii = idx & 15;
        sm.qst[d*TI + ii] = g_q[(bh*Nn + i0 + ii)*Dd + d];
    }
    #pragma unroll
    for (int r = 0; r < 4; r++) {
        int idx = t + r*ATH;              // 1024 = EDIM*Dd
        int c = idx >> 6, d = idx & 63;
        sm.Wes[c*Dd + d] = We[c*INNER + h*Dd + d];
    }
    if (t < TI) sm.mns[t] = g_means[i0 + t];
    if (t < Dd) sm.bes[t] = be[h*Dd + t];
    __syncthreads();

    // ---- fused qwe / qbe
    {
        const int c = t >> 4, il = t & 15;
        float s = 0.f;
        #pragma unroll
        for (int d = 0; d < Dd; d++) s += sm.qst[d*TI + il] * sm.Wes[c*Dd + d];
        sm.qwe[il*EDIM + c] = s;
        if (t < TI) {
            float qb = 0.f;
            #pragma unroll
            for (int d = 0; d < Dd; d++) qb += sm.qst[d*TI + t] * sm.bes[d];
            sm.qbe[t] = qb;
        }
    }
    __syncthreads();

    const u64* qst2 = reinterpret_cast<const u64*>(sm.qst);            // [d*8 + q8]
    const ulonglong2* qwep = reinterpret_cast<const ulonglong2*>(sm.qwe);  // [ii*4+w]
    const float* xsf = sm.xs;
    const ulonglong2* edgesP = reinterpret_cast<const ulonglong2*>(edges);
    const ulonglong2* eTp = reinterpret_cast<const ulonglong2*>(g_eT4);

    // ================= phase A: 16 rows per thread, K from g_kT (L2) ==========
    {
        const int j = t;
        const long eT0 = ((long)(b*Nn + i0)*4)*Nn + j;
        const int adjBase = (b*Nn + i0)*Nn + j;
        ulonglong2 EB[2][4];
        float adjB[2];
        #pragma unroll
        for (int s = 0; s < 2; s++) {
            const long rb = eT0 + (long)s*4*Nn;
            EB[s][0] = eTp[rb + 0*Nn]; EB[s][1] = eTp[rb + 1*Nn];
            EB[s][2] = eTp[rb + 2*Nn]; EB[s][3] = eTp[rb + 3*Nn];
            adjB[s] = adjacency[adjBase + s*Nn];
        }

        const float* kbase = g_kT + (size_t)bh*Dd*Nn + j;
        u64 aP[8];
        #pragma unroll
        for (int q = 0; q < 8; q++) aP[q] = 0ull;
        #pragma unroll 8
        for (int d = 0; d < Dd; d++) {
            float kv = kbase[d*Nn];
            u64 kd = pk2(kv, kv);
            #pragma unroll
            for (int q = 0; q < 8; q++) aP[q] = ffma2(qst2[d*8 + q], kd, aP[q]);
        }

        float xtmp[4];
        float4* xrow = reinterpret_cast<float4*>(&sm.xs[j*XSTR]);
        #pragma unroll
        for (int s = 0; s < TI; s++) {
            const int cur = s & 1;
            ulonglong2 E0 = EB[cur][0], E1 = EB[cur][1];
            ulonglong2 E2 = EB[cur][2], E3 = EB[cur][3];
            float adjc = adjB[cur];
            if (s < TI-2) {
                const long nb = eT0 + (long)(s+2)*4*Nn;
                EB[cur][0] = eTp[nb + 0*Nn]; EB[cur][1] = eTp[nb + 1*Nn];
                EB[cur][2] = eTp[nb + 2*Nn]; EB[cur][3] = eTp[nb + 3*Nn];
                adjB[cur] = adjacency[adjBase + (s+2)*Nn];
            }
            ulonglong2 Q0 = qwep[s*4+0], Q1 = qwep[s*4+1];
            ulonglong2 Q2 = qwep[s*4+2], Q3 = qwep[s*4+3];
            u64 etp = 0ull;
            etp = ffma2(E0.x, Q0.x, etp); etp = ffma2(E0.y, Q0.y, etp);
            etp = ffma2(E1.x, Q1.x, etp); etp = ffma2(E1.y, Q1.y, etp);
            etp = ffma2(E2.x, Q2.x, etp); etp = ffma2(E2.y, Q2.y, etp);
            etp = ffma2(E3.x, Q3.x, etp); etp = ffma2(E3.y, Q3.y, etp);
            float2 etv = up2(etp);
            float2 av = up2(aP[s >> 1]);
            float a = (s & 1) ? av.y : av.x;
            float sim = (a + etv.x + etv.y + sm.qbe[s]) * 0.125f;
            xtmp[s & 3] = __expf(sim - sm.mns[s]) * adjc;
            if ((s & 3) == 3)
                xrow[s >> 2] = make_float4(xtmp[0], xtmp[1], xtmp[2], xtmp[3]);
        }
    }
    __syncthreads();

    // ================= phase B1: x @ v, V from g_v (L2) =================
    {
        const int d = t & 63, g = t >> 6;
        u64 p0=0ull,p1=0ull,p2=0ull,p3=0ull,p4=0ull,p5=0ull,p6=0ull,p7=0ull;
        const float* vbase = g_v + (size_t)bh*Nn*Dd + d;
        #pragma unroll 8
        for (int jj = g; jj < Nn; jj += 4) {
            float vv = vbase[jj*Dd];
            u64 vp = pk2(vv, vv);
            const ulonglong2* xrp = reinterpret_cast<const ulonglong2*>(&sm.xs[jj*XSTR]);
            ulonglong2 xA = xrp[0], xB = xrp[1], xC = xrp[2], xD = xrp[3];
            p0 = ffma2(xA.x, vp, p0); p1 = ffma2(xA.y, vp, p1);
            p2 = ffma2(xB.x, vp, p2); p3 = ffma2(xB.y, vp, p3);
            p4 = ffma2(xC.x, vp, p4); p5 = ffma2(xC.y, vp, p5);
            p6 = ffma2(xD.x, vp, p6); p7 = ffma2(xD.y, vp, p7);
        }
        ulonglong2* ro = reinterpret_cast<ulonglong2*>(&sm.red_out[(g*Dd + d)*4]);
        ro[0] = make_ulonglong2(p0, p1);
        ro[1] = make_ulonglong2(p2, p3);
        ro[2] = make_ulonglong2(p4, p5);
        ro[3] = make_ulonglong2(p6, p7);
    }
    // ================= phase B2: x . edges (original layout) + den ======
    {
        const int c4 = t & 3, g2 = (t >> 2) & 3, u = t >> 4;
        const int i = i0 + u;
        const ulonglong2* ebase = edgesP + (long)(b*Nn + i)*Nn*4;
        u64 ae0 = 0ull, ae1 = 0ull;
        float sden = 0.f;
        #pragma unroll 8
        for (int r = 0; r < 64; r++) {
            int jj = g2 + r*4;
            float x = xsf[jj*XSTR + u];
            u64 xp = pk2(x, x);
            ulonglong2 e = ebase[jj*4 + c4];
            ae0 = ffma2(e.x, xp, ae0);
            ae1 = ffma2(e.y, xp, ae1);
            sden += x;
        }
        *reinterpret_cast<ulonglong2*>(&sm.red_ae[(u*4 + g2)*4 + c4]) =
            make_ulonglong2(ae0, ae1);
        if (c4 == 0) sm.red_den[u*4 + g2] = sden;
    }
    __syncthreads();
    // ---- reduce aE + den
    {
        const int u = t >> 4, c = t & 15;
        const int c4 = c >> 2, comp = c & 3;
        float s = 0.f;
        #pragma unroll
        for (int g2 = 0; g2 < 4; g2++) {
            float4 p = sm.red_ae[(u*4 + g2)*4 + c4];
            s += (comp==0) ? p.x : ((comp==1) ? p.y : ((comp==2) ? p.z : p.w));
        }
        sm.aes[u*EDIM + c] = s;
        if (t < CH)
            sm.den[t] = sm.red_den[t*4+0] + sm.red_den[t*4+1]
                      + sm.red_den[t*4+2] + sm.red_den[t*4+3];
    }
    __syncthreads();
    // ================= finalize 16 rows (4 per thread) ==========
    {
        const int d = t & 63, uh = t >> 6;
        #pragma unroll
        for (int p2 = 0; p2 < 4; p2++) {
            const int u = uh + 4*p2;      // p = u>>2 = p2, comp = u&3 = uh
            float rs = 0.f;
            #pragma unroll
            for (int g = 0; g < 4; g++) {
                float4 r = sm.red_out[(g*Dd + d)*4 + p2];
                rs += (uh==0) ? r.x : ((uh==1) ? r.y : ((uh==2) ? r.z : r.w));
            }
            float eterm = 0.f;
            #pragma unroll
            for (int c = 0; c < EDIM; c++) eterm += sm.aes[u*EDIM + c] * sm.Wes[c*Dd + d];
            float dn = sm.den[u];
            float scale = (dn != 0.f) ? (1.f / dn) : 0.f;
            float bterm = (dn != 0.f) ? sm.bes[d] : 0.f;
            const int i = i0 + u;
            out[(b*Nn + i)*INNER + h*Dd + d] = (rs + eterm) * scale + bterm;
        }
    }
}

// ---------------- launch ----------------
extern "C" void kernel_launch(void* const* d_in, const int* in_sizes, int n_in,
                              void* d_out, int out_size)
{
    const float* nodes = (const float*)d_in[0];
    const float* edges = (const float*)d_in[1];
    const float* adj   = (const float*)d_in[2];
    const float* Wq = (const float*)d_in[3]; const float* bq = (const float*)d_in[4];
    const float* Wk = (const float*)d_in[5]; const float* bk = (const float*)d_in[6];
    const float* Wv = (const float*)d_in[7]; const float* bv = (const float*)d_in[8];
    const float* We = (const float*)d_in[9]; const float* be = (const float*)d_in[10];
    float* out = (float*)d_out;

    cudaFuncSetAttribute(attn_kernel, cudaFuncAttributeMaxDynamicSharedMemorySize,
                         (int)sizeof(AttnSm));

    prep_kernel<<<896, 128>>>(nodes, edges, Wq, bq, Wk, bk, Wv, bv);
    means_kernel<<<Nn, 256>>>(We, be);
    attn_kernel<<<dim3(Nn/TI, BHn), ATH, sizeof(AttnSm)>>>(edges, adj, We, be, out);
}

// round 15
// speedup vs baseline: 1.1289x; 1.1289x over previous
#include <cuda_runtime.h>
#include <math.h>

#define Bn 2
#define Nn 256
#define INDIM 256
#define EDIM 16
#define Hh 8
#define Dd 64
#define INNER 512
#define BHn 16
#define TI 16
#define CH 16
#define ATH 256
#define XSTR 20   // float stride per j-row of xs

typedef unsigned long long u64;

// ---- packed f32x2 helpers (Blackwell FFMA2) ----
__device__ __forceinline__ u64 pk2(float lo, float hi) {
    u64 r;
    asm("mov.b64 %0, {%1, %2};" : "=l"(r)
        : "r"(__float_as_uint(lo)), "r"(__float_as_uint(hi)));
    return r;
}
__device__ __forceinline__ u64 ffma2(u64 a, u64 b, u64 c) {
    u64 d;
    asm("fma.rn.f32x2 %0, %1, %2, %3;" : "=l"(d) : "l"(a), "l"(b), "l"(c));
    return d;
}
__device__ __forceinline__ float2 up2(u64 p) {
    unsigned int lo, hi;
    asm("mov.b64 {%0, %1}, %2;" : "=r"(lo), "=r"(hi) : "l"(p));
    return make_float2(__uint_as_float(lo), __uint_as_float(hi));
}

// ---------------- scratch (device globals; no allocation allowed) ----------------
__device__ float g_q[BHn*Nn*Dd];        // [bh][i][d]
__device__ float g_kT[BHn*Dd*Nn];       // [bh][d][j]  (transposed, for attn + means)
__device__ float g_v[BHn*Nn*Dd];        // [bh][j][d]
__device__ float g_means[Nn];           // row means of sim for bh==0 (reference quirk)
__device__ float4 g_eT4[Bn*Nn*4*Nn];    // [b][i][c4][j] channel-quad-major edges (8.4MB)

// ---------------- edge transpose: [b][i][j][c] -> [b][i][c4][j] (float4) ---------
__global__ void __launch_bounds__(256) etr_kernel(const float* __restrict__ edges)
{
    const int b = blockIdx.y, i = blockIdx.x, t = threadIdx.x;
    __shared__ float4 es[4*Nn];   // [c4][j], 16KB
    const float4* ep = reinterpret_cast<const float4*>(edges)
                     + ((size_t)(b*Nn + i)*Nn + t)*4;
    #pragma unroll
    for (int c4 = 0; c4 < 4; c4++) es[c4*Nn + t] = ep[c4];
    __syncthreads();
    float4* outp = g_eT4 + (size_t)(b*Nn + i)*4*Nn;
    #pragma unroll
    for (int r = 0; r < 4; r++) {
        int idx = t + r*256;
        outp[idx] = es[idx];
    }
}

// ---------------- projection GEMM: double-buffered smem, FFMA2, K -> kT only -----
__global__ void __launch_bounds__(128) proj_kernel(
    const float* __restrict__ nodes,
    const float* __restrict__ Wq, const float* __restrict__ bq,
    const float* __restrict__ Wk, const float* __restrict__ bk,
    const float* __restrict__ Wv, const float* __restrict__ bv)
{
    const int which = blockIdx.z;
    const float* W    = (which==0) ? Wq : ((which==1) ? Wk : Wv);
    const float* bias = (which==0) ? bq : ((which==1) ? bk : bv);
    __shared__ float As[2][32][36];
    __shared__ float Bs[2][32][64];
    __shared__ float TT[32][69];      // K transpose staging
    const int row0 = blockIdx.y * 32;
    const int col0 = blockIdx.x * 64;
    const int t = threadIdx.x;
    const int tx = t & 15, ty = t >> 4;

    u64 acc[4][2];
    #pragma unroll
    for (int u = 0; u < 4; u++) { acc[u][0] = 0ull; acc[u][1] = 0ull; }

    {
        #pragma unroll
        for (int r = 0; r < 2; r++) {
            int idx = t + r*128;
            int row = idx >> 3, kq = idx & 7;
            float4 nv = *reinterpret_cast<const float4*>(&nodes[(row0+row)*INDIM + kq*4]);
            As[0][kq*4+0][row] = nv.x; As[0][kq*4+1][row] = nv.y;
            As[0][kq*4+2][row] = nv.z; As[0][kq*4+3][row] = nv.w;
        }
        #pragma unroll
        for (int r = 0; r < 4; r++) {
            int idx = t + r*128;
            int kk = idx >> 4, c4 = idx & 15;
            *reinterpret_cast<float4*>(&Bs[0][kk][c4*4]) =
                *reinterpret_cast<const float4*>(&W[kk*INNER + col0 + c4*4]);
        }
    }

    #pragma unroll
    for (int it = 0; it < 8; it++) {
        const int p = it & 1;
        __syncthreads();
        if (it < 7) {
            const int k0 = (it+1) * 32;
            const int pn = p ^ 1;
            #pragma unroll
            for (int r = 0; r < 2; r++) {
                int idx = t + r*128;
                int row = idx >> 3, kq = idx & 7;
                float4 nv = *reinterpret_cast<const float4*>(&nodes[(row0+row)*INDIM + k0 + kq*4]);
                As[pn][kq*4+0][row] = nv.x; As[pn][kq*4+1][row] = nv.y;
                As[pn][kq*4+2][row] = nv.z; As[pn][kq*4+3][row] = nv.w;
            }
            #pragma unroll
            for (int r = 0; r < 4; r++) {
                int idx = t + r*128;
                int kk = idx >> 4, c4 = idx & 15;
                *reinterpret_cast<float4*>(&Bs[pn][kk][c4*4]) =
                    *reinterpret_cast<const float4*>(&W[(k0+kk)*INNER + col0 + c4*4]);
            }
        }
        #pragma unroll
        for (int k = 0; k < 32; k++) {
            float4 a4 = *reinterpret_cast<const float4*>(&As[p][k][ty*4]);
            ulonglong2 b2 = *reinterpret_cast<const ulonglong2*>(&Bs[p][k][tx*4]);
            u64 ap;
            ap = pk2(a4.x, a4.x); acc[0][0]=ffma2(b2.x,ap,acc[0][0]); acc[0][1]=ffma2(b2.y,ap,acc[0][1]);
            ap = pk2(a4.y, a4.y); acc[1][0]=ffma2(b2.x,ap,acc[1][0]); acc[1][1]=ffma2(b2.y,ap,acc[1][1]);
            ap = pk2(a4.z, a4.z); acc[2][0]=ffma2(b2.x,ap,acc[2][0]); acc[2][1]=ffma2(b2.y,ap,acc[2][1]);
            ap = pk2(a4.w, a4.w); acc[3][0]=ffma2(b2.x,ap,acc[3][0]); acc[3][1]=ffma2(b2.y,ap,acc[3][1]);
        }
    }

    const int b = row0 >> 8;
    const int i0l = row0 & 255;
    const int h = col0 >> 6;
    const int bh = b*Hh + h;
    float4 bias4 = *reinterpret_cast<const float4*>(&bias[col0 + tx*4]);

    if (which != 1) {
        float* dst = (which == 0) ? g_q : g_v;
        #pragma unroll
        for (int u = 0; u < 4; u++) {
            int i = i0l + ty*4 + u;
            float2 c01 = up2(acc[u][0]);
            float2 c23 = up2(acc[u][1]);
            float4 val = make_float4(c01.x+bias4.x, c01.y+bias4.y,
                                     c23.x+bias4.z, c23.y+bias4.w);
            *reinterpret_cast<float4*>(&dst[(bh*Nn + i)*Dd + tx*4]) = val;
        }
    } else {
        #pragma unroll
        for (int u = 0; u < 4; u++) {
            int il = ty*4 + u;
            float2 c01 = up2(acc[u][0]);
            float2 c23 = up2(acc[u][1]);
            TT[il][tx*4+0] = c01.x+bias4.x; TT[il][tx*4+1] = c01.y+bias4.y;
            TT[il][tx*4+2] = c23.x+bias4.z; TT[il][tx*4+3] = c23.y+bias4.w;
        }
        __syncthreads();
        #pragma unroll
        for (int w = 0; w < 16; w++) {
            int idx = t + w*128;               // 2048 = 64 d x 32 i
            int d = idx >> 5, il = idx & 31;
            g_kT[(bh*Dd + d)*Nn + i0l + il] = TT[il][d];
        }
    }
}

// ---------------- means: analytic row-mean (kbar from g_kT, coalesced) -----------
__global__ void __launch_bounds__(256) means_kernel(const float* __restrict__ We,
                                                    const float* __restrict__ be)
{
    const int i = blockIdx.x;
    const int t = threadIdx.x;
    const int lane = t & 31, wid = t >> 5;
    __shared__ float qsm[Dd];
    __shared__ float WesM[EDIM*Dd];
    __shared__ float besM[Dd];
    __shared__ float qwes[EDIM];
    __shared__ float qbes_s;
    __shared__ float eParts[8][EDIM];
    __shared__ float esum[EDIM];
    __shared__ float kbar[Dd];

    if (t < Dd) { qsm[t] = g_q[i*Dd + t]; besM[t] = be[t]; }
    #pragma unroll
    for (int r = 0; r < 4; r++) {
        int idx = t + r*256;
        WesM[idx] = We[(idx >> 6)*INNER + (idx & 63)];
    }
    // ---- edge row-sum over j (thread = j), coalesced eT4 reads
    {
        const float4* eTp = g_eT4 + (size_t)i*4*Nn;
        float4 e0 = eTp[0*Nn + t], e1 = eTp[1*Nn + t];
        float4 e2 = eTp[2*Nn + t], e3 = eTp[3*Nn + t];
        float ev[EDIM] = { e0.x,e0.y,e0.z,e0.w, e1.x,e1.y,e1.z,e1.w,
                           e2.x,e2.y,e2.z,e2.w, e3.x,e3.y,e3.z,e3.w };
        #pragma unroll
        for (int c = 0; c < EDIM; c++) {
            float v = ev[c];
            #pragma unroll
            for (int o = 16; o > 0; o >>= 1) v += __shfl_down_sync(0xffffffffu, v, o);
            if (lane == 0) eParts[wid][c] = v;
        }
    }
    // ---- kbar from g_kT: warp wid handles d = wid*8 .. wid*8+7 (coalesced over j)
    {
        #pragma unroll
        for (int dd = 0; dd < 8; dd++) {
            int d = wid*8 + dd;
            const float* kr = g_kT + d*Nn;      // bh = 0
            float s = 0.f;
            #pragma unroll
            for (int r = 0; r < 8; r++) s += kr[lane + r*32];
            #pragma unroll
            for (int o = 16; o > 0; o >>= 1) s += __shfl_down_sync(0xffffffffu, s, o);
            if (lane == 0) kbar[d] = s;
        }
    }
    __syncthreads();
    if (t < EDIM) {
        float s = 0.f;
        #pragma unroll
        for (int w = 0; w < 8; w++) s += eParts[w][t];
        esum[t] = s;
        float qw = 0.f;
        #pragma unroll
        for (int d = 0; d < Dd; d++) qw += qsm[d] * WesM[t*Dd + d];
        qwes[t] = qw;
    } else if (t == EDIM) {
        float qb = 0.f;
        #pragma unroll
        for (int d = 0; d < Dd; d++) qb += qsm[d] * besM[d];
        qbes_s = qb;
    }
    __syncthreads();
    if (t < 32) {
        float v = qsm[t]*kbar[t] + qsm[t+32]*kbar[t+32];
        if (t < EDIM) v += esum[t]*qwes[t];
        #pragma unroll
        for (int o = 16; o > 0; o >>= 1) v += __shfl_down_sync(0xffffffffu, v, o);
        if (t == 0) g_means[i] = 0.125f * (v * (1.0f/Nn) + qbes_s);
    }
}

// ---------------- fused attention v11: TI=16, 256 thr, 2 blocks/SM ---------------
struct AttnSm {
    float  xs[Nn*XSTR];         // 20K
    float4 red_out[4*Dd*4];     // 16K [g][d][p]
    float4 red_ae[CH*4*4];      // 4K  [u][g2][c4]
    float  qst[Dd*TI];          // 4K  [d][ii]
    float  qwe[TI*EDIM];        // 1K  [ii][c]
    float  Wes[EDIM*Dd];        // 4K  [c][d]
    float  aes[CH*EDIM];        // 1K
    float  red_den[CH*4];
    float  qbe[TI];
    float  mns[TI];
    float  bes[Dd];
    float  den[CH];
};

__global__ void __launch_bounds__(ATH, 2) attn_kernel(
    const float* __restrict__ edges, const float* __restrict__ adjacency,
    const float* __restrict__ We, const float* __restrict__ be,
    float* __restrict__ out)
{
    extern __shared__ char smraw[];
    AttnSm& sm = *reinterpret_cast<AttnSm*>(smraw);
    const int t  = threadIdx.x;
    const int bh = blockIdx.y;
    const int b  = bh >> 3, h = bh & 7;
    const int i0 = blockIdx.x * TI;

    // ---- small tile loads
    #pragma unroll
    for (int r = 0; r < 4; r++) {
        int idx = t + r*ATH;              // 1024 = Dd*TI
        int d = idx >> 4, ii = idx & 15;
        sm.qst[d*TI + ii] = g_q[(bh*Nn + i0 + ii)*Dd + d];
    }
    #pragma unroll
    for (int r = 0; r < 4; r++) {
        int idx = t + r*ATH;              // 1024 = EDIM*Dd
        int c = idx >> 6, d = idx & 63;
        sm.Wes[c*Dd + d] = We[c*INNER + h*Dd + d];
    }
    if (t < TI) sm.mns[t] = g_means[i0 + t];
    if (t < Dd) sm.bes[t] = be[h*Dd + t];
    __syncthreads();

    // ---- fused qwe / qbe
    {
        const int c = t >> 4, il = t & 15;
        float s = 0.f;
        #pragma unroll
        for (int d = 0; d < Dd; d++) s += sm.qst[d*TI + il] * sm.Wes[c*Dd + d];
        sm.qwe[il*EDIM + c] = s;
        if (t < TI) {
            float qb = 0.f;
            #pragma unroll
            for (int d = 0; d < Dd; d++) qb += sm.qst[d*TI + t] * sm.bes[d];
            sm.qbe[t] = qb;
        }
    }
    __syncthreads();

    const u64* qst2 = reinterpret_cast<const u64*>(sm.qst);            // [d*8 + q8]
    const ulonglong2* qwep = reinterpret_cast<const ulonglong2*>(sm.qwe);  // [ii*4+w]
    const float* xsf = sm.xs;
    const ulonglong2* edgesP = reinterpret_cast<const ulonglong2*>(edges);
    const ulonglong2* eTp = reinterpret_cast<const ulonglong2*>(g_eT4);

    // ================= phase A: 16 rows per thread, K from g_kT (L2) ==========
    {
        const int j = t;
        const long eT0 = ((long)(b*Nn + i0)*4)*Nn + j;
        const int adjBase = (b*Nn + i0)*Nn + j;
        ulonglong2 EB[2][4];
        float adjB[2];
        #pragma unroll
        for (int s = 0; s < 2; s++) {
            const long rb = eT0 + (long)s*4*Nn;
            EB[s][0] = eTp[rb + 0*Nn]; EB[s][1] = eTp[rb + 1*Nn];
            EB[s][2] = eTp[rb + 2*Nn]; EB[s][3] = eTp[rb + 3*Nn];
            adjB[s] = adjacency[adjBase + s*Nn];
        }

        const float* kbase = g_kT + (size_t)bh*Dd*Nn + j;
        u64 aP[8];
        #pragma unroll
        for (int q = 0; q < 8; q++) aP[q] = 0ull;
        #pragma unroll 8
        for (int d = 0; d < Dd; d++) {
            float kv = kbase[d*Nn];
            u64 kd = pk2(kv, kv);
            #pragma unroll
            for (int q = 0; q < 8; q++) aP[q] = ffma2(qst2[d*8 + q], kd, aP[q]);
        }

        float xtmp[4];
        float4* xrow = reinterpret_cast<float4*>(&sm.xs[j*XSTR]);
        #pragma unroll
        for (int s = 0; s < TI; s++) {
            const int cur = s & 1;
            ulonglong2 E0 = EB[cur][0], E1 = EB[cur][1];
            ulonglong2 E2 = EB[cur][2], E3 = EB[cur][3];
            float adjc = adjB[cur];
            if (s < TI-2) {
                const long nb = eT0 + (long)(s+2)*4*Nn;
                EB[cur][0] = eTp[nb + 0*Nn]; EB[cur][1] = eTp[nb + 1*Nn];
                EB[cur][2] = eTp[nb + 2*Nn]; EB[cur][3] = eTp[nb + 3*Nn];
                adjB[cur] = adjacency[adjBase + (s+2)*Nn];
            }
            ulonglong2 Q0 = qwep[s*4+0], Q1 = qwep[s*4+1];
            ulonglong2 Q2 = qwep[s*4+2], Q3 = qwep[s*4+3];
            u64 etp = 0ull;
            etp = ffma2(E0.x, Q0.x, etp); etp = ffma2(E0.y, Q0.y, etp);
            etp = ffma2(E1.x, Q1.x, etp); etp = ffma2(E1.y, Q1.y, etp);
            etp = ffma2(E2.x, Q2.x, etp); etp = ffma2(E2.y, Q2.y, etp);
            etp = ffma2(E3.x, Q3.x, etp); etp = ffma2(E3.y, Q3.y, etp);
            float2 etv = up2(etp);
            float2 av = up2(aP[s >> 1]);
            float a = (s & 1) ? av.y : av.x;
            float sim = (a + etv.x + etv.y + sm.qbe[s]) * 0.125f;
            xtmp[s & 3] = __expf(sim - sm.mns[s]) * adjc;
            if ((s & 3) == 3)
                xrow[s >> 2] = make_float4(xtmp[0], xtmp[1], xtmp[2], xtmp[3]);
        }
    }
    __syncthreads();

    // ================= phase B1: x @ v, V from g_v (L2) =================
    {
        const int d = t & 63, g = t >> 6;
        u64 p0=0ull,p1=0ull,p2=0ull,p3=0ull,p4=0ull,p5=0ull,p6=0ull,p7=0ull;
        const float* vbase = g_v + (size_t)bh*Nn*Dd + d;
        #pragma unroll 8
        for (int jj = g; jj < Nn; jj += 4) {
            float vv = vbase[jj*Dd];
            u64 vp = pk2(vv, vv);
            const ulonglong2* xrp = reinterpret_cast<const ulonglong2*>(&sm.xs[jj*XSTR]);
            ulonglong2 xA = xrp[0], xB = xrp[1], xC = xrp[2], xD = xrp[3];
            p0 = ffma2(xA.x, vp, p0); p1 = ffma2(xA.y, vp, p1);
            p2 = ffma2(xB.x, vp, p2); p3 = ffma2(xB.y, vp, p3);
            p4 = ffma2(xC.x, vp, p4); p5 = ffma2(xC.y, vp, p5);
            p6 = ffma2(xD.x, vp, p6); p7 = ffma2(xD.y, vp, p7);
        }
        ulonglong2* ro = reinterpret_cast<ulonglong2*>(&sm.red_out[(g*Dd + d)*4]);
        ro[0] = make_ulonglong2(p0, p1);
        ro[1] = make_ulonglong2(p2, p3);
        ro[2] = make_ulonglong2(p4, p5);
        ro[3] = make_ulonglong2(p6, p7);
    }
    // ================= phase B2: x . edges (original layout) + den ======
    {
        const int c4 = t & 3, g2 = (t >> 2) & 3, u = t >> 4;
        const int i = i0 + u;
        const ulonglong2* ebase = edgesP + (long)(b*Nn + i)*Nn*4;
        u64 ae0 = 0ull, ae1 = 0ull;
        float sden = 0.f;
        #pragma unroll 8
        for (int r = 0; r < 64; r++) {
            int jj = g2 + r*4;
            float x = xsf[jj*XSTR + u];
            u64 xp = pk2(x, x);
            ulonglong2 e = ebase[jj*4 + c4];
            ae0 = ffma2(e.x, xp, ae0);
            ae1 = ffma2(e.y, xp, ae1);
            sden += x;
        }
        *reinterpret_cast<ulonglong2*>(&sm.red_ae[(u*4 + g2)*4 + c4]) =
            make_ulonglong2(ae0, ae1);
        if (c4 == 0) sm.red_den[u*4 + g2] = sden;
    }
    __syncthreads();
    // ---- reduce aE + den
    {
        const int u = t >> 4, c = t & 15;
        const int c4 = c >> 2, comp = c & 3;
        float s = 0.f;
        #pragma unroll
        for (int g2 = 0; g2 < 4; g2++) {
            float4 p = sm.red_ae[(u*4 + g2)*4 + c4];
            s += (comp==0) ? p.x : ((comp==1) ? p.y : ((comp==2) ? p.z : p.w));
        }
        sm.aes[u*EDIM + c] = s;
        if (t < CH)
            sm.den[t] = sm.red_den[t*4+0] + sm.red_den[t*4+1]
                      + sm.red_den[t*4+2] + sm.red_den[t*4+3];
    }
    __syncthreads();
    // ================= finalize 16 rows (4 per thread) ==========
    {
        const int d = t & 63, uh = t >> 6;
        #pragma unroll
        for (int p2 = 0; p2 < 4; p2++) {
            const int u = uh + 4*p2;      // p = u>>2 = p2, comp = u&3 = uh
            float rs = 0.f;
            #pragma unroll
            for (int g = 0; g < 4; g++) {
                float4 r = sm.red_out[(g*Dd + d)*4 + p2];
                rs += (uh==0) ? r.x : ((uh==1) ? r.y : ((uh==2) ? r.z : r.w));
            }
            float eterm = 0.f;
            #pragma unroll
            for (int c = 0; c < EDIM; c++) eterm += sm.aes[u*EDIM + c] * sm.Wes[c*Dd + d];
            float dn = sm.den[u];
            float scale = (dn != 0.f) ? (1.f / dn) : 0.f;
            float bterm = (dn != 0.f) ? sm.bes[d] : 0.f;
            const int i = i0 + u;
            out[(b*Nn + i)*INNER + h*Dd + d] = (rs + eterm) * scale + bterm;
        }
    }
}

// ---------------- launch ----------------
extern "C" void kernel_launch(void* const* d_in, const int* in_sizes, int n_in,
                              void* d_out, int out_size)
{
    const float* nodes = (const float*)d_in[0];
    const float* edges = (const float*)d_in[1];
    const float* adj   = (const float*)d_in[2];
    const float* Wq = (const float*)d_in[3]; const float* bq = (const float*)d_in[4];
    const float* Wk = (const float*)d_in[5]; const float* bk = (const float*)d_in[6];
    const float* Wv = (const float*)d_in[7]; const float* bv = (const float*)d_in[8];
    const float* We = (const float*)d_in[9]; const float* be = (const float*)d_in[10];
    float* out = (float*)d_out;

    cudaFuncSetAttribute(attn_kernel, cudaFuncAttributeMaxDynamicSharedMemorySize,
                         (int)sizeof(AttnSm));

    etr_kernel<<<dim3(Nn, Bn), 256>>>(edges);
    proj_kernel<<<dim3(8, 16, 3), 128>>>(nodes, Wq, bq, Wk, bk, Wv, bv);
    means_kernel<<<Nn, 256>>>(We, be);
    attn_kernel<<<dim3(Nn/TI, BHn), ATH, sizeof(AttnSm)>>>(edges, adj, We, be, out);
}